// round 14
// baseline (speedup 1.0000x reference)
#include <cuda_runtime.h>
#include <cstddef>
#include <cstdint>

// Butterfly n=1024, log_n=10, increasing stride, + bias. 32768 rows.
//
// R13 = R12 with the stage-8/9 wiring bug fixed.
// 256 threads/block, TWO pairs per thread {k, k+256} => stages 8 AND 9 are
// thread-local, eliminating the stage-8 smem round + full-block barrier.
// Exchange rounds: stages 0-4 shfl_xor, stages 5-7 smem (barriers scoped
// 64/128/256). Deferred scaling (2 FMA/stage). TMA bulk 3-slot ring, dist 2.
// 4 blocks/SM (GRID=592).
//
// Stage-8 row identities (loadT applies rsw at i=8):
//   pair a (bit8=0): P8a = elem k      (scale c8a), S8a = elem k+256 (d8a)
//   pair b (bit8=1): P8b = elem k+768  (scale c8b), S8b = elem k+512 (d8b)
// Stage 9 (RAW twiddles, explicit element wiring):
//   pair a = elems (k, k+512)     = (P8a, S8b)
//   pair b = elems (k+256, k+768) = (S8a, P8b)

constexpr int TPB  = 256;
constexpr int GRID = 592;

__device__ __forceinline__ void barx(int id, int cnt) {
    asm volatile("bar.sync %0, %1;" :: "r"(id), "r"(cnt) : "memory");
}
__device__ __forceinline__ void mbar_init(uint32_t a, uint32_t cnt) {
    asm volatile("mbarrier.init.shared.b64 [%0], %1;" :: "r"(a), "r"(cnt) : "memory");
}
__device__ __forceinline__ void mbar_expect_tx(uint32_t a, uint32_t bytes) {
    asm volatile("mbarrier.arrive.expect_tx.shared.b64 _, [%0], %1;" :: "r"(a), "r"(bytes) : "memory");
}
__device__ __forceinline__ void bulk_ld(uint32_t dst, const void* src, uint32_t bytes, uint32_t mbar) {
    asm volatile("cp.async.bulk.shared::cta.global.mbarrier::complete_tx::bytes [%0], [%1], %2, [%3];"
                 :: "r"(dst), "l"(src), "r"(bytes), "r"(mbar) : "memory");
}
__device__ __forceinline__ void mbar_wait(uint32_t a, uint32_t parity) {
    asm volatile(
        "{\n\t"
        ".reg .pred P;\n\t"
        "LW%=:\n\t"
        "mbarrier.try_wait.parity.acquire.cta.shared::cta.b64 P, [%0], %1, 0x989680;\n\t"
        "@P bra.uni LD%=;\n\t"
        "bra.uni LW%=;\n\t"
        "LD%=:\n\t"
        "}"
        :: "r"(a), "r"(parity) : "memory");
}

// pre-permuted twiddle for (pair p, stage i): validated steering (R2/R4/R9)
__device__ __forceinline__ float4 loadT(const float4* tw4, int p, int i) {
    float4 t = tw4[i * 512 + p];
    const bool rsw = (i <= 8) && (((p >> i) & 1) != 0);
    const bool csw = (i >= 1) && (((p >> (i - 1)) & 1) != 0);
    if (rsw) t = make_float4(t.z, t.w, t.x, t.y);
    if (csw) t = make_float4(t.y, t.x, t.w, t.z);
    return t;
}

__global__ __launch_bounds__(TPB, 4)
void butterfly_kernel(const float* __restrict__ x,
                      const float* __restrict__ tw,
                      const float* __restrict__ bias,
                      float* __restrict__ out,
                      int nrows)
{
    __shared__ __align__(16) float ring[3][1024];     // 12 KB: 3 slots x 1 row
    __shared__ float bufA[512], bufB[512], bufC[512]; // 6 KB exchange buffers
    __shared__ __align__(8) unsigned long long mbar[3];
    const int k = threadIdx.x;      // pair a = k, pair b = k + 256
    const int w = k >> 5;           // warp 0..7

    const uint32_t mb0 = (uint32_t)__cvta_generic_to_shared(&mbar[0]);
    const uint32_t rg0 = (uint32_t)__cvta_generic_to_shared(&ring[0][0]);

    if (k == 0) {
        mbar_init(mb0,      1);
        mbar_init(mb0 + 8,  1);
        mbar_init(mb0 + 16, 1);
    }

    // ---- deferred-scaling coefficients, both pairs -------------------------
    const float4* tw4 = reinterpret_cast<const float4*>(tw);
    float alpA[8], betA[8], alpB[8], betB[8];
    float cPa = 1.f, sQa = 1.f, cPb = 1.f, sQb = 1.f;
#pragma unroll
    for (int j = 0; j < 8; ++j) {
        const float4 t = loadT(tw4, k, j);
        alpA[j] = (t.y * sQa) / (t.x * cPa);
        betA[j] = (t.w * sQa) / (t.z * cPa);
        const float4 u = loadT(tw4, k + 256, j);
        alpB[j] = (u.y * sQb) / (u.x * cPb);
        betB[j] = (u.w * sQb) / (u.z * cPb);
        // partner sent-scales for the values received after stage j
        const int qa = k ^ (1 << j);
        float ca = 1.f;
        for (int i = 0; i < j; ++i) ca *= loadT(tw4, qa, i).x;
        sQa = loadT(tw4, qa, j).z * ca;
        const int qb = (k + 256) ^ (1 << j);
        float cb = 1.f;
        for (int i = 0; i < j; ++i) cb *= loadT(tw4, qb, i).x;
        sQb = loadT(tw4, qb, j).z * cb;
        cPa *= t.x;  cPb *= u.x;
    }
    // stage 8 (thread-local): deferred coefs + output scales (loadT w/ rsw)
    const float4 t8a = loadT(tw4, k, 8);
    const float4 t8b = loadT(tw4, k + 256, 8);
    const float a8A = (t8a.y * sQa) / (t8a.x * cPa);
    const float b8A = (t8a.w * sQa) / (t8a.z * cPa);
    const float a8B = (t8b.y * sQb) / (t8b.x * cPb);
    const float b8B = (t8b.w * sQb) / (t8b.z * cPb);
    const float c8a = t8a.x * cPa, d8a = t8a.z * cPa;   // P8a(elem k), S8a(elem k+256)
    const float c8b = t8b.x * cPb, d8b = t8b.z * cPb;   // P8b(elem k+768), S8b(elem k+512)

    // stage 9: RAW twiddles, explicit element wiring
    const float4 t9a = tw4[9 * 512 + k];         // pair (k, k+512)
    const float4 t9b = tw4[9 * 512 + k + 256];   // pair (k+256, k+768)
    const float A00 = t9a.x * c8a, A01 = t9a.y * d8b;   // out[k]     from (P8a,S8b)
    const float A10 = t9a.z * c8a, A11 = t9a.w * d8b;   // out[k+512]
    const float B00 = t9b.x * d8a, B01 = t9b.y * c8b;   // out[k+256] from (S8a,P8b)
    const float B10 = t9b.z * d8a, B11 = t9b.w * c8b;   // out[k+768]
    const float bias0 = bias[k],       bias1 = bias[k + 256];
    const float bias2 = bias[k + 512], bias3 = bias[k + 768];

    __syncthreads();                 // mbarriers initialized

    // ---- prologue: issue bulk loads for iterations 0 and 1 ----------------
    const int r00 = blockIdx.x;
    if (k == 0) {
#pragma unroll
        for (int d = 0; d < 2; ++d) {
            const int r = r00 + d * GRID;
            if (r < nrows) {
                mbar_expect_tx(mb0 + 8u * d, 4096u);
                bulk_ld(rg0 + 4096u * d, x + (size_t)r * 1024, 4096u, mb0 + 8u * d);
            }
        }
    }

    int r = r00;
    int slot = 0, par = 0;
    while (r < nrows) {
        // ---- issue bulk load for iteration i+2 -----------------------------
        if (k == 0) {
            const int rn = r + 2 * GRID;
            if (rn < nrows) {
                int s2 = slot + 2; if (s2 >= 3) s2 -= 3;
                mbar_expect_tx(mb0 + 8u * s2, 4096u);
                bulk_ld(rg0 + 4096u * s2, x + (size_t)rn * 1024, 4096u, mb0 + 8u * s2);
            }
        }

        // ---- wait for this row's data, read own operands -------------------
        mbar_wait(mb0 + 8u * slot, par);
        const float2 va = *reinterpret_cast<const float2*>(&ring[slot][2 * k]);       // pair a
        const float2 vb = *reinterpret_cast<const float2*>(&ring[slot][512 + 2 * k]); // pair b

        float Pa = va.x, Qa = va.y;
        float Pb = vb.x, Qb = vb.y;

#pragma unroll
        for (int j = 0; j < 8; ++j) {
            const float Sa = fmaf(betA[j], Qa, Pa);
            Pa             = fmaf(alpA[j], Qa, Pa);
            const float Sb = fmaf(betB[j], Qb, Pb);
            Pb             = fmaf(alpB[j], Qb, Pb);

            if (j <= 4) {
                const int d = 1 << j;
                Qa = __shfl_xor_sync(0xffffffffu, Sa, d);
                Qb = __shfl_xor_sync(0xffffffffu, Sb, d);
            } else if (j == 5) {
                bufA[k] = Sa; bufA[256 + k] = Sb;
                barx(1 + (w >> 1), 64);            // warp-pair {w, w^1}
                Qa = bufA[k ^ 32]; Qb = bufA[256 + (k ^ 32)];
            } else if (j == 6) {
                bufB[k] = Sa; bufB[256 + k] = Sb;
                barx(5 + (w >> 2), 128);           // warp quad
                Qa = bufB[k ^ 64]; Qb = bufB[256 + (k ^ 64)];
            } else {  // j == 7
                bufC[k] = Sa; bufC[256 + k] = Sb;
                __syncthreads();                   // 256-thread block sync
                Qa = bufC[k ^ 128]; Qb = bufC[256 + (k ^ 128)];
            }
        }

        // ---- stage 8 local, deferred ----------------------------------------
        const float P8a = fmaf(a8A, Qa, Pa);       // elem k      (hat, scale c8a)
        const float S8a = fmaf(b8A, Qa, Pa);       // elem k+256  (hat, scale d8a)
        const float P8b = fmaf(a8B, Qb, Pb);       // elem k+768  (hat, scale c8b)
        const float S8b = fmaf(b8B, Qb, Pb);       // elem k+512  (hat, scale d8b)

        // ---- stage 9 local: pair a=(k,k+512)=(P8a,S8b), pair b=(k+256,k+768)=(S8a,P8b)
        const float za0 = fmaf(A00, P8a, fmaf(A01, S8b, bias0));
        const float za1 = fmaf(A10, P8a, fmaf(A11, S8b, bias2));
        const float zb0 = fmaf(B00, S8a, fmaf(B01, P8b, bias1));
        const float zb1 = fmaf(B10, S8a, fmaf(B11, P8b, bias3));

        float* o = out + (size_t)r * 1024;
        __stcs(o + k,       za0);
        __stcs(o + k + 256, zb0);
        __stcs(o + k + 512, za1);
        __stcs(o + k + 768, zb1);

        r += GRID;
        ++slot;
        if (slot == 3) { slot = 0; par ^= 1; }
    }
}

extern "C" void kernel_launch(void* const* d_in, const int* in_sizes, int n_in,
                              void* d_out, int out_size)
{
    const float* x  = nullptr;
    const float* tw = nullptr;
    const float* bs = nullptr;
    long long x_elems = 0;
    for (int i = 0; i < n_in; ++i) {
        if (in_sizes[i] == 20480)     tw = (const float*)d_in[i];
        else if (in_sizes[i] == 1024) bs = (const float*)d_in[i];
        else { x = (const float*)d_in[i]; x_elems = in_sizes[i]; }
    }
    const int nrows = (int)(x_elems / 1024);

    butterfly_kernel<<<GRID, TPB>>>(x, tw, bs, (float*)d_out, nrows);
}

// round 15
// speedup vs baseline: 1.1382x; 1.1382x over previous
#include <cuda_runtime.h>
#include <cstddef>
#include <cstdint>

// Butterfly n=1024, log_n=10, increasing stride, + bias. 32768 rows.
//
// R14 = R13 topology (256 thr, 2 pairs/thread {k,k+256}; stages 8,9 thread-
// local; 3 smem exchange rounds w/ barriers scoped 64/128/256; deferred
// scaling; TMA bulk ring) x R11 row-ILP (TWO rows per iteration):
//   - barriers/row: 1.5 (vs 3 in R13, 1.33 in R11)
//   - exchange smem bytes/row: 12KB (vs 16KB in R11)
//   - 4 independent FMA/shfl chains per lockstep region
// launch_bounds(256,3), GRID=444 (3 blocks/SM).

constexpr int TPB  = 256;
constexpr int GRID = 444;

__device__ __forceinline__ void barx(int id, int cnt) {
    asm volatile("bar.sync %0, %1;" :: "r"(id), "r"(cnt) : "memory");
}
__device__ __forceinline__ void mbar_init(uint32_t a, uint32_t cnt) {
    asm volatile("mbarrier.init.shared.b64 [%0], %1;" :: "r"(a), "r"(cnt) : "memory");
}
__device__ __forceinline__ void mbar_expect_tx(uint32_t a, uint32_t bytes) {
    asm volatile("mbarrier.arrive.expect_tx.shared.b64 _, [%0], %1;" :: "r"(a), "r"(bytes) : "memory");
}
__device__ __forceinline__ void bulk_ld(uint32_t dst, const void* src, uint32_t bytes, uint32_t mbar) {
    asm volatile("cp.async.bulk.shared::cta.global.mbarrier::complete_tx::bytes [%0], [%1], %2, [%3];"
                 :: "r"(dst), "l"(src), "r"(bytes), "r"(mbar) : "memory");
}
__device__ __forceinline__ void mbar_wait(uint32_t a, uint32_t parity) {
    asm volatile(
        "{\n\t"
        ".reg .pred P;\n\t"
        "LW%=:\n\t"
        "mbarrier.try_wait.parity.acquire.cta.shared::cta.b64 P, [%0], %1, 0x989680;\n\t"
        "@P bra.uni LD%=;\n\t"
        "bra.uni LW%=;\n\t"
        "LD%=:\n\t"
        "}"
        :: "r"(a), "r"(parity) : "memory");
}

// pre-permuted twiddle for (pair p, stage i): validated steering
__device__ __forceinline__ float4 loadT(const float4* tw4, int p, int i) {
    float4 t = tw4[i * 512 + p];
    const bool rsw = (i <= 8) && (((p >> i) & 1) != 0);
    const bool csw = (i >= 1) && (((p >> (i - 1)) & 1) != 0);
    if (rsw) t = make_float4(t.z, t.w, t.x, t.y);
    if (csw) t = make_float4(t.y, t.x, t.w, t.z);
    return t;
}

__global__ __launch_bounds__(TPB, 3)
void butterfly_kernel(const float* __restrict__ x,
                      const float* __restrict__ tw,
                      const float* __restrict__ bias,
                      float* __restrict__ out,
                      int nrows)
{
    __shared__ __align__(16) float ring[3][2048];        // 24 KB: 3 slots x 2 rows
    __shared__ float bufA[1024], bufB[1024], bufC[1024]; // 12 KB exchange buffers
    __shared__ __align__(8) unsigned long long mbar[3];
    const int k = threadIdx.x;      // pair a = k, pair b = k + 256
    const int w = k >> 5;           // warp 0..7

    const uint32_t mb0 = (uint32_t)__cvta_generic_to_shared(&mbar[0]);
    const uint32_t rg0 = (uint32_t)__cvta_generic_to_shared(&ring[0][0]);

    if (k == 0) {
        mbar_init(mb0,      1);
        mbar_init(mb0 + 8,  1);
        mbar_init(mb0 + 16, 1);
    }

    // ---- deferred-scaling coefficients, both pairs -------------------------
    const float4* tw4 = reinterpret_cast<const float4*>(tw);
    float alpA[8], betA[8], alpB[8], betB[8];
    float cPa = 1.f, sQa = 1.f, cPb = 1.f, sQb = 1.f;
#pragma unroll
    for (int j = 0; j < 8; ++j) {
        const float4 t = loadT(tw4, k, j);
        alpA[j] = (t.y * sQa) / (t.x * cPa);
        betA[j] = (t.w * sQa) / (t.z * cPa);
        const float4 u = loadT(tw4, k + 256, j);
        alpB[j] = (u.y * sQb) / (u.x * cPb);
        betB[j] = (u.w * sQb) / (u.z * cPb);
        const int qa = k ^ (1 << j);
        float ca = 1.f;
        for (int i = 0; i < j; ++i) ca *= loadT(tw4, qa, i).x;
        sQa = loadT(tw4, qa, j).z * ca;
        const int qb = (k + 256) ^ (1 << j);
        float cb = 1.f;
        for (int i = 0; i < j; ++i) cb *= loadT(tw4, qb, i).x;
        sQb = loadT(tw4, qb, j).z * cb;
        cPa *= t.x;  cPb *= u.x;
    }
    // stage 8 (thread-local): deferred coefs + output scales (loadT w/ rsw)
    const float4 t8a = loadT(tw4, k, 8);
    const float4 t8b = loadT(tw4, k + 256, 8);
    const float a8A = (t8a.y * sQa) / (t8a.x * cPa);
    const float b8A = (t8a.w * sQa) / (t8a.z * cPa);
    const float a8B = (t8b.y * sQb) / (t8b.x * cPb);
    const float b8B = (t8b.w * sQb) / (t8b.z * cPb);
    const float c8a = t8a.x * cPa, d8a = t8a.z * cPa;   // P8a(elem k), S8a(elem k+256)
    const float c8b = t8b.x * cPb, d8b = t8b.z * cPb;   // P8b(elem k+768), S8b(elem k+512)

    // stage 9: RAW twiddles, explicit element wiring (validated in R13)
    const float4 t9a = tw4[9 * 512 + k];         // pair (k, k+512)
    const float4 t9b = tw4[9 * 512 + k + 256];   // pair (k+256, k+768)
    const float A00 = t9a.x * c8a, A01 = t9a.y * d8b;   // out[k]     from (P8a,S8b)
    const float A10 = t9a.z * c8a, A11 = t9a.w * d8b;   // out[k+512]
    const float B00 = t9b.x * d8a, B01 = t9b.y * c8b;   // out[k+256] from (S8a,P8b)
    const float B10 = t9b.z * d8a, B11 = t9b.w * c8b;   // out[k+768]
    const float bias0 = bias[k],       bias1 = bias[k + 256];
    const float bias2 = bias[k + 512], bias3 = bias[k + 768];

    const int npairs = (nrows + 1) >> 1;
    __syncthreads();                 // mbarriers initialized

    // ---- prologue: issue bulk loads for iterations 0 and 1 ----------------
    const int pi0 = blockIdx.x;
    if (k == 0) {
#pragma unroll
        for (int d = 0; d < 2; ++d) {
            const int p = pi0 + d * GRID;
            if (p < npairs) {
                const int r0 = 2 * p;
                const uint32_t bytes = (r0 + 1 < nrows) ? 8192u : 4096u;
                mbar_expect_tx(mb0 + 8u * d, bytes);
                bulk_ld(rg0 + 8192u * d, x + (size_t)r0 * 1024, bytes, mb0 + 8u * d);
            }
        }
    }

    int pi = pi0;
    int slot = 0, par = 0;
    while (pi < npairs) {
        // ---- issue bulk load for iteration i+2 -----------------------------
        if (k == 0) {
            const int p = pi + 2 * GRID;
            if (p < npairs) {
                int s2 = slot + 2; if (s2 >= 3) s2 -= 3;
                const int r0 = 2 * p;
                const uint32_t bytes = (r0 + 1 < nrows) ? 8192u : 4096u;
                mbar_expect_tx(mb0 + 8u * s2, bytes);
                bulk_ld(rg0 + 8192u * s2, x + (size_t)r0 * 1024, bytes, mb0 + 8u * s2);
            }
        }

        // ---- wait for this iteration's data, read own operands -------------
        mbar_wait(mb0 + 8u * slot, par);
        const float2 va0 = *reinterpret_cast<const float2*>(&ring[slot][2 * k]);        // row0 pair a
        const float2 vb0 = *reinterpret_cast<const float2*>(&ring[slot][512 + 2 * k]);  // row0 pair b
        const float2 va1 = *reinterpret_cast<const float2*>(&ring[slot][1024 + 2 * k]); // row1 pair a
        const float2 vb1 = *reinterpret_cast<const float2*>(&ring[slot][1536 + 2 * k]); // row1 pair b

        float Pa0 = va0.x, Qa0 = va0.y, Pb0 = vb0.x, Qb0 = vb0.y;
        float Pa1 = va1.x, Qa1 = va1.y, Pb1 = vb1.x, Qb1 = vb1.y;

#pragma unroll
        for (int j = 0; j < 8; ++j) {
            const float Sa0 = fmaf(betA[j], Qa0, Pa0);
            Pa0             = fmaf(alpA[j], Qa0, Pa0);
            const float Sb0 = fmaf(betB[j], Qb0, Pb0);
            Pb0             = fmaf(alpB[j], Qb0, Pb0);
            const float Sa1 = fmaf(betA[j], Qa1, Pa1);
            Pa1             = fmaf(alpA[j], Qa1, Pa1);
            const float Sb1 = fmaf(betB[j], Qb1, Pb1);
            Pb1             = fmaf(alpB[j], Qb1, Pb1);

            if (j <= 4) {
                const int d = 1 << j;
                Qa0 = __shfl_xor_sync(0xffffffffu, Sa0, d);
                Qb0 = __shfl_xor_sync(0xffffffffu, Sb0, d);
                Qa1 = __shfl_xor_sync(0xffffffffu, Sa1, d);
                Qb1 = __shfl_xor_sync(0xffffffffu, Sb1, d);
            } else if (j == 5) {
                bufA[k] = Sa0; bufA[256 + k] = Sb0;
                bufA[512 + k] = Sa1; bufA[768 + k] = Sb1;
                barx(1 + (w >> 1), 64);            // warp-pair {w, w^1}
                Qa0 = bufA[k ^ 32];         Qb0 = bufA[256 + (k ^ 32)];
                Qa1 = bufA[512 + (k ^ 32)]; Qb1 = bufA[768 + (k ^ 32)];
            } else if (j == 6) {
                bufB[k] = Sa0; bufB[256 + k] = Sb0;
                bufB[512 + k] = Sa1; bufB[768 + k] = Sb1;
                barx(5 + (w >> 2), 128);           // warp quad
                Qa0 = bufB[k ^ 64];         Qb0 = bufB[256 + (k ^ 64)];
                Qa1 = bufB[512 + (k ^ 64)]; Qb1 = bufB[768 + (k ^ 64)];
            } else {  // j == 7
                bufC[k] = Sa0; bufC[256 + k] = Sb0;
                bufC[512 + k] = Sa1; bufC[768 + k] = Sb1;
                __syncthreads();                   // 256-thread block sync
                Qa0 = bufC[k ^ 128];         Qb0 = bufC[256 + (k ^ 128)];
                Qa1 = bufC[512 + (k ^ 128)]; Qb1 = bufC[768 + (k ^ 128)];
            }
        }

        // ---- stage 8 local, deferred ----------------------------------------
        const float P8a0 = fmaf(a8A, Qa0, Pa0);
        const float S8a0 = fmaf(b8A, Qa0, Pa0);
        const float P8b0 = fmaf(a8B, Qb0, Pb0);
        const float S8b0 = fmaf(b8B, Qb0, Pb0);
        const float P8a1 = fmaf(a8A, Qa1, Pa1);
        const float S8a1 = fmaf(b8A, Qa1, Pa1);
        const float P8b1 = fmaf(a8B, Qb1, Pb1);
        const float S8b1 = fmaf(b8B, Qb1, Pb1);

        // ---- stage 9 local + folds + bias -----------------------------------
        const float za0_0 = fmaf(A00, P8a0, fmaf(A01, S8b0, bias0));
        const float za1_0 = fmaf(A10, P8a0, fmaf(A11, S8b0, bias2));
        const float zb0_0 = fmaf(B00, S8a0, fmaf(B01, P8b0, bias1));
        const float zb1_0 = fmaf(B10, S8a0, fmaf(B11, P8b0, bias3));
        const float za0_1 = fmaf(A00, P8a1, fmaf(A01, S8b1, bias0));
        const float za1_1 = fmaf(A10, P8a1, fmaf(A11, S8b1, bias2));
        const float zb0_1 = fmaf(B00, S8a1, fmaf(B01, P8b1, bias1));
        const float zb1_1 = fmaf(B10, S8a1, fmaf(B11, P8b1, bias3));

        const int r0 = 2 * pi, r1 = 2 * pi + 1;
        {
            float* o = out + (size_t)r0 * 1024;
            __stcs(o + k,       za0_0);
            __stcs(o + k + 256, zb0_0);
            __stcs(o + k + 512, za1_0);
            __stcs(o + k + 768, zb1_0);
        }
        if (r1 < nrows) {
            float* o = out + (size_t)r1 * 1024;
            __stcs(o + k,       za0_1);
            __stcs(o + k + 256, zb0_1);
            __stcs(o + k + 512, za1_1);
            __stcs(o + k + 768, zb1_1);
        }

        pi += GRID;
        ++slot;
        if (slot == 3) { slot = 0; par ^= 1; }
    }
}

extern "C" void kernel_launch(void* const* d_in, const int* in_sizes, int n_in,
                              void* d_out, int out_size)
{
    const float* x  = nullptr;
    const float* tw = nullptr;
    const float* bs = nullptr;
    long long x_elems = 0;
    for (int i = 0; i < n_in; ++i) {
        if (in_sizes[i] == 20480)     tw = (const float*)d_in[i];
        else if (in_sizes[i] == 1024) bs = (const float*)d_in[i];
        else { x = (const float*)d_in[i]; x_elems = in_sizes[i]; }
    }
    const int nrows = (int)(x_elems / 1024);

    butterfly_kernel<<<GRID, TPB>>>(x, tw, bs, (float*)d_out, nrows);
}